// round 1
// baseline (speedup 1.0000x reference)
#include <cuda_runtime.h>
#include <cuda_bf16.h>

#define N_NODES 100000
#define N_EDGES 1600000
#define NF 128
#define NEG_SLOPE 0.02f
#define EPSN 1e-5f

// ---------------- scratch (static device memory; no allocs) ----------------
__device__ float g_h[(size_t)N_NODES * NF];
__device__ float g_m[(size_t)N_NODES * NF];
__device__ float g_raw[(size_t)N_NODES * NF];
__device__ int   g_deg[N_NODES];
__device__ int   g_rowptr[N_NODES + 1];
__device__ int   g_cursor[N_NODES];
__device__ int   g_col[N_EDGES];
__device__ float g_stats[2 * NF];
__device__ float g_scale[NF];
__device__ float g_shift[NF];

// ---------------- packed f32x2 helpers (FFMA2 path) ----------------
__device__ __forceinline__ unsigned long long pk2(float lo, float hi) {
    unsigned long long r;
    asm("mov.b64 %0, {%1,%2};" : "=l"(r) : "f"(lo), "f"(hi));
    return r;
}
__device__ __forceinline__ unsigned long long fma2(unsigned long long a,
                                                   unsigned long long b,
                                                   unsigned long long c) {
    unsigned long long d;
    asm("fma.rn.f32x2 %0, %1, %2, %3;" : "=l"(d) : "l"(a), "l"(b), "l"(c));
    return d;
}
__device__ __forceinline__ float2 upk2(unsigned long long v) {
    float2 f;
    asm("mov.b64 {%0,%1}, %2;" : "=f"(f.x), "=f"(f.y) : "l"(v));
    return f;
}

__device__ __forceinline__ float4 max4(float4 a, float4 b) {
    float4 r;
    r.x = fmaxf(a.x, b.x); r.y = fmaxf(a.y, b.y);
    r.z = fmaxf(a.z, b.z); r.w = fmaxf(a.w, b.w);
    return r;
}

// ---------------- CSR build ----------------
__global__ void k_zero_deg(int* deg) {
    int i = blockIdx.x * 256 + threadIdx.x;
    if (i < N_NODES) deg[i] = 0;
}

__global__ void k_count(const int* __restrict__ dst, int* __restrict__ deg) {
    int i = blockIdx.x * 256 + threadIdx.x;
    if (i < N_EDGES) atomicAdd(&deg[dst[i]], 1);
}

__global__ void k_scan(const int* __restrict__ deg, int* __restrict__ rowptr,
                       int* __restrict__ cursor) {
    __shared__ int sh[1024];
    int t = threadIdx.x;
    const int C = (N_NODES + 1023) / 1024;  // 98
    int base = t * C;
    int s = 0;
    for (int i = 0; i < C; i++) {
        int idx = base + i;
        if (idx < N_NODES) s += deg[idx];
    }
    sh[t] = s;
    __syncthreads();
    // Hillis-Steele inclusive scan
    for (int d = 1; d < 1024; d <<= 1) {
        int v = (t >= d) ? sh[t - d] : 0;
        __syncthreads();
        sh[t] += v;
        __syncthreads();
    }
    int run = sh[t] - s;  // exclusive prefix
    for (int i = 0; i < C; i++) {
        int idx = base + i;
        if (idx < N_NODES) {
            rowptr[idx] = run;
            cursor[idx] = run;
            run += deg[idx];
        }
    }
    if (t == 1023) rowptr[N_NODES] = sh[1023];
}

__global__ void k_fill(const int* __restrict__ src, const int* __restrict__ dst,
                       int* __restrict__ cursor, int* __restrict__ col) {
    int i = blockIdx.x * 256 + threadIdx.x;
    if (i < N_EDGES) {
        int d = dst[i];
        int p = atomicAdd(&cursor[d], 1);
        col[p] = src[i];
    }
}

// ---------------- segment-max gather: one warp per dst node ----------------
__global__ void k_gather(const float4* __restrict__ h4, const int* __restrict__ rowptr,
                         const int* __restrict__ col, float4* __restrict__ m4) {
    int node = blockIdx.x * 8 + (threadIdx.x >> 5);
    if (node >= N_NODES) return;
    int lane = threadIdx.x & 31;
    int beg = __ldg(&rowptr[node]);
    int end = __ldg(&rowptr[node + 1]);
    const float NINF = __int_as_float(0xff800000);
    float4 a; a.x = a.y = a.z = a.w = NINF;
    int e = beg;
    for (; e + 3 < end; e += 4) {
        int s0 = __ldg(&col[e]);
        int s1 = __ldg(&col[e + 1]);
        int s2 = __ldg(&col[e + 2]);
        int s3 = __ldg(&col[e + 3]);
        float4 v0 = __ldg(&h4[(size_t)s0 * 32 + lane]);
        float4 v1 = __ldg(&h4[(size_t)s1 * 32 + lane]);
        float4 v2 = __ldg(&h4[(size_t)s2 * 32 + lane]);
        float4 v3 = __ldg(&h4[(size_t)s3 * 32 + lane]);
        a = max4(a, max4(max4(v0, v1), max4(v2, v3)));
    }
    for (; e < end; e++) {
        int s = __ldg(&col[e]);
        a = max4(a, __ldg(&h4[(size_t)s * 32 + lane]));
    }
    if (beg == end) { a.x = a.y = a.z = a.w = 0.0f; }  // empty segment -> 0
    m4[(size_t)node * 32 + lane] = a;
}

// ---------------- fused dual GEMM + bias + column stats ----------------
// out[i,o] = sum_k m[i,k]*Wl[o,k] + sum_k h[i,k]*Wr[o,k] + bias[o]
// Treated as K=256 GEMM with A=[m|h], B=[Wl|Wr]. 128x128 tile per block,
// 8x8 register tile per thread, packed f32x2 FMA accumulation.
__global__ __launch_bounds__(256)
void k_gemm(const float* __restrict__ Am, const float* __restrict__ Ah,
            const float* __restrict__ Wl, const float* __restrict__ Wr,
            const float* __restrict__ bias,
            float* __restrict__ out, float* __restrict__ stats) {
    __shared__ float As[2][16][132];
    __shared__ float Bs[2][16][132];
    __shared__ float red[16][128];

    const int tid = threadIdx.x;
    const int tx = tid & 15;
    const int ty = tid >> 4;
    const int row0 = blockIdx.x * 128;

    unsigned long long acc[8][4];
#pragma unroll
    for (int i = 0; i < 8; i++)
#pragma unroll
        for (int j = 0; j < 4; j++) acc[i][j] = 0ull;

    float4 aReg[2], bReg[2];

    // chunk loader: chunk c covers k in [c*16, c*16+16) of the virtual K=256
#define LOAD_A(c)                                                          \
    {                                                                      \
        int k0 = (c) * 16;                                                 \
        const float* Ap = (k0 < 128) ? Am : Ah;                            \
        int koff = k0 & 127;                                               \
        _Pragma("unroll") for (int s = 0; s < 2; s++) {                    \
            int lin = tid * 2 + s;                                         \
            int rr = lin >> 2, jj = lin & 3;                               \
            int grow = row0 + rr;                                          \
            if (grow < N_NODES)                                            \
                aReg[s] = *(const float4*)&Ap[(size_t)grow * 128 + koff + jj * 4]; \
            else                                                           \
                aReg[s] = make_float4(0.f, 0.f, 0.f, 0.f);                 \
        }                                                                  \
    }
#define LOAD_B(c)                                                          \
    {                                                                      \
        int k0 = (c) * 16;                                                 \
        const float* Wp = (k0 < 128) ? Wl : Wr;                            \
        int koff = k0 & 127;                                               \
        _Pragma("unroll") for (int s = 0; s < 2; s++) {                    \
            int lin = tid * 2 + s;                                         \
            int oo = lin >> 2, jj = lin & 3;                               \
            bReg[s] = *(const float4*)&Wp[oo * 128 + koff + jj * 4];       \
        }                                                                  \
    }
#define STORE_A(buf)                                                       \
    _Pragma("unroll") for (int s = 0; s < 2; s++) {                        \
        int lin = tid * 2 + s;                                             \
        int rr = lin >> 2, jj = lin & 3;                                   \
        As[buf][jj * 4 + 0][rr] = aReg[s].x;                               \
        As[buf][jj * 4 + 1][rr] = aReg[s].y;                               \
        As[buf][jj * 4 + 2][rr] = aReg[s].z;                               \
        As[buf][jj * 4 + 3][rr] = aReg[s].w;                               \
    }
#define STORE_B(buf)                                                       \
    _Pragma("unroll") for (int s = 0; s < 2; s++) {                        \
        int lin = tid * 2 + s;                                             \
        int rr = lin >> 2, jj = lin & 3;                                   \
        Bs[buf][jj * 4 + 0][rr] = bReg[s].x;                               \
        Bs[buf][jj * 4 + 1][rr] = bReg[s].y;                               \
        Bs[buf][jj * 4 + 2][rr] = bReg[s].z;                               \
        Bs[buf][jj * 4 + 3][rr] = bReg[s].w;                               \
    }

    LOAD_A(0); LOAD_B(0);
    STORE_A(0); STORE_B(0);

#pragma unroll 1
    for (int c = 0; c < 16; c++) {
        __syncthreads();
        int buf = c & 1;
        if (c < 15) { LOAD_A(c + 1); LOAD_B(c + 1); }
#pragma unroll
        for (int kk = 0; kk < 16; kk++) {
            float4 a0 = *(const float4*)&As[buf][kk][ty * 8];
            float4 a1 = *(const float4*)&As[buf][kk][ty * 8 + 4];
            float4 b0 = *(const float4*)&Bs[buf][kk][tx * 8];
            float4 b1 = *(const float4*)&Bs[buf][kk][tx * 8 + 4];
            unsigned long long bp0 = pk2(b0.x, b0.y);
            unsigned long long bp1 = pk2(b0.z, b0.w);
            unsigned long long bp2 = pk2(b1.x, b1.y);
            unsigned long long bp3 = pk2(b1.z, b1.w);
            float av[8] = {a0.x, a0.y, a0.z, a0.w, a1.x, a1.y, a1.z, a1.w};
#pragma unroll
            for (int i = 0; i < 8; i++) {
                unsigned long long ap = pk2(av[i], av[i]);
                acc[i][0] = fma2(ap, bp0, acc[i][0]);
                acc[i][1] = fma2(ap, bp1, acc[i][1]);
                acc[i][2] = fma2(ap, bp2, acc[i][2]);
                acc[i][3] = fma2(ap, bp3, acc[i][3]);
            }
        }
        if (c < 15) { STORE_A(buf ^ 1); STORE_B(buf ^ 1); }
    }

    // epilogue: bias + store + column stats
    float bvals[8];
#pragma unroll
    for (int j = 0; j < 8; j++) bvals[j] = __ldg(&bias[tx * 8 + j]);

    float csum[8], csq[8];
#pragma unroll
    for (int j = 0; j < 8; j++) { csum[j] = 0.f; csq[j] = 0.f; }

#pragma unroll
    for (int i = 0; i < 8; i++) {
        int gr = row0 + ty * 8 + i;
        if (gr < N_NODES) {
            float v[8];
#pragma unroll
            for (int j = 0; j < 4; j++) {
                float2 f = upk2(acc[i][j]);
                v[2 * j] = f.x + bvals[2 * j];
                v[2 * j + 1] = f.y + bvals[2 * j + 1];
            }
            float4 o0 = make_float4(v[0], v[1], v[2], v[3]);
            float4 o1 = make_float4(v[4], v[5], v[6], v[7]);
            *(float4*)&out[(size_t)gr * 128 + tx * 8] = o0;
            *(float4*)&out[(size_t)gr * 128 + tx * 8 + 4] = o1;
#pragma unroll
            for (int j = 0; j < 8; j++) { csum[j] += v[j]; csq[j] += v[j] * v[j]; }
        }
    }

    __syncthreads();
#pragma unroll
    for (int j = 0; j < 8; j++) red[ty][tx * 8 + j] = csum[j];
    __syncthreads();
    if (tid < 128) {
        float s = 0.f;
#pragma unroll
        for (int t2 = 0; t2 < 16; t2++) s += red[t2][tid];
        atomicAdd(&stats[tid], s);
    }
    __syncthreads();
#pragma unroll
    for (int j = 0; j < 8; j++) red[ty][tx * 8 + j] = csq[j];
    __syncthreads();
    if (tid < 128) {
        float s = 0.f;
#pragma unroll
        for (int t2 = 0; t2 < 16; t2++) s += red[t2][tid];
        atomicAdd(&stats[128 + tid], s);
    }
#undef LOAD_A
#undef LOAD_B
#undef STORE_A
#undef STORE_B
}

// ---------------- GraphNorm stats ----------------
__global__ void k_zero_stats(float* st) { st[threadIdx.x] = 0.f; }

__global__ void k_stats(const float* __restrict__ st, const float* __restrict__ gamma,
                        const float* __restrict__ beta, const float* __restrict__ alpha,
                        float* __restrict__ scale, float* __restrict__ shift) {
    int c = threadIdx.x;
    const float invN = 1.0f / (float)N_NODES;
    float mu = st[c] * invN;
    float a = alpha[c];
    // E[(h - a*mu)^2] = E[h^2] + mu^2*(a^2 - 2a)
    float var = st[c + 128] * invN + mu * mu * (a * a - 2.f * a);
    float r = rsqrtf(var + EPSN);
    float g = gamma[c];
    scale[c] = g * r;
    shift[c] = beta[c] - g * a * mu * r;
}

// ---------------- normalize + LeakyReLU ----------------
__global__ void k_norm(const float4* __restrict__ raw, const float4* __restrict__ sc4,
                       const float4* __restrict__ sh4, float4* __restrict__ hout) {
    int i = blockIdx.x * 256 + threadIdx.x;
    if (i >= N_NODES * 32) return;
    int c4 = i & 31;
    float4 s = __ldg(&sc4[c4]);
    float4 t = __ldg(&sh4[c4]);
    float4 v = raw[i];
    float4 o;
    o.x = s.x * v.x + t.x; o.x = (o.x > 0.f) ? o.x : NEG_SLOPE * o.x;
    o.y = s.y * v.y + t.y; o.y = (o.y > 0.f) ? o.y : NEG_SLOPE * o.y;
    o.z = s.z * v.z + t.z; o.z = (o.z > 0.f) ? o.z : NEG_SLOPE * o.z;
    o.w = s.w * v.w + t.w; o.w = (o.w > 0.f) ? o.w : NEG_SLOPE * o.w;
    hout[i] = o;
}

// ---------------- final SAGEConv (NF->3) + tanh*0.5 ----------------
__global__ void k_final(const float4* __restrict__ m4, const float4* __restrict__ h4,
                        const float* __restrict__ Wlo, const float* __restrict__ Wro,
                        const float* __restrict__ blo, float* __restrict__ out) {
    __shared__ float4 swl[3][32];
    __shared__ float4 swr[3][32];
    __shared__ float sb[3];
    int tid = threadIdx.x;
    if (tid < 96) {
        int o = tid >> 5, l = tid & 31;
        swl[o][l] = ((const float4*)Wlo)[o * 32 + l];
        swr[o][l] = ((const float4*)Wro)[o * 32 + l];
    }
    if (tid < 3) sb[tid] = blo[tid];
    __syncthreads();

    int node = blockIdx.x * 8 + (tid >> 5);
    if (node >= N_NODES) return;
    int lane = tid & 31;
    float4 mv = m4[(size_t)node * 32 + lane];
    float4 hv = h4[(size_t)node * 32 + lane];
    float p[3];
#pragma unroll
    for (int o = 0; o < 3; o++) {
        float4 wl = swl[o][lane];
        float4 wr = swr[o][lane];
        p[o] = mv.x * wl.x + mv.y * wl.y + mv.z * wl.z + mv.w * wl.w +
               hv.x * wr.x + hv.y * wr.y + hv.z * wr.z + hv.w * wr.w;
    }
#pragma unroll
    for (int d = 16; d; d >>= 1) {
#pragma unroll
        for (int o = 0; o < 3; o++) p[o] += __shfl_down_sync(0xffffffffu, p[o], d);
    }
    if (lane == 0) {
#pragma unroll
        for (int o = 0; o < 3; o++)
            out[(size_t)node * 3 + o] = tanhf(p[o] + sb[o]) * 0.5f;
    }
}

// ---------------- host launcher ----------------
extern "C" void kernel_launch(void* const* d_in, const int* in_sizes, int n_in,
                              void* d_out, int out_size) {
    const float* x     = (const float*)d_in[0];
    const int*   ei    = (const int*)d_in[1];
    const float* Wl    = (const float*)d_in[2];
    const float* bl    = (const float*)d_in[3];
    const float* Wr    = (const float*)d_in[4];
    const float* Wlo   = (const float*)d_in[5];
    const float* blo   = (const float*)d_in[6];
    const float* Wro   = (const float*)d_in[7];
    const float* gamma = (const float*)d_in[8];
    const float* beta  = (const float*)d_in[9];
    const float* alpha = (const float*)d_in[10];

    float *h, *m, *raw, *stats, *scale, *shift;
    int *deg, *rowptr, *cursor, *col;
    cudaGetSymbolAddress((void**)&h, g_h);
    cudaGetSymbolAddress((void**)&m, g_m);
    cudaGetSymbolAddress((void**)&raw, g_raw);
    cudaGetSymbolAddress((void**)&stats, g_stats);
    cudaGetSymbolAddress((void**)&scale, g_scale);
    cudaGetSymbolAddress((void**)&shift, g_shift);
    cudaGetSymbolAddress((void**)&deg, g_deg);
    cudaGetSymbolAddress((void**)&rowptr, g_rowptr);
    cudaGetSymbolAddress((void**)&cursor, g_cursor);
    cudaGetSymbolAddress((void**)&col, g_col);

    const int* src = ei;
    const int* dst = ei + N_EDGES;

    // CSR build (per call; deterministic output, fill order irrelevant for max)
    k_zero_deg<<<(N_NODES + 255) / 256, 256>>>(deg);
    k_count<<<(N_EDGES + 255) / 256, 256>>>(dst, deg);
    k_scan<<<1, 1024>>>(deg, rowptr, cursor);
    k_fill<<<(N_EDGES + 255) / 256, 256>>>(src, dst, cursor, col);

    const float* hcur = x;
    for (int L = 0; L < 6; L++) {
        k_gather<<<(N_NODES + 7) / 8, 256>>>((const float4*)hcur, rowptr, col,
                                             (float4*)m);
        k_zero_stats<<<1, 256>>>(stats);
        k_gemm<<<(N_NODES + 127) / 128, 256>>>(m, hcur, Wl + L * NF * NF,
                                               Wr + L * NF * NF, bl + L * NF, raw,
                                               stats);
        k_stats<<<1, 128>>>(stats, gamma + L * NF, beta + L * NF, alpha + L * NF,
                            scale, shift);
        k_norm<<<(N_NODES * 32 + 255) / 256, 256>>>((const float4*)raw,
                                                    (const float4*)scale,
                                                    (const float4*)shift,
                                                    (float4*)h);
        hcur = h;
    }
    k_gather<<<(N_NODES + 7) / 8, 256>>>((const float4*)hcur, rowptr, col,
                                         (float4*)m);
    k_final<<<(N_NODES + 7) / 8, 256>>>((const float4*)m, (const float4*)hcur, Wlo,
                                        Wro, blo, (float*)d_out);
}

// round 3
// speedup vs baseline: 1.5507x; 1.5507x over previous
#include <cuda_runtime.h>
#include <cuda_bf16.h>
#include <cstdint>

#define N_NODES 100000
#define N_EDGES 1600000
#define NF 128
#define NEG_SLOPE 0.02f
#define EPSN 1e-5f

// tcgen05 only exists on the arch-specific / family-specific targets.
// The harness also builds a plain compute_103 PTX pass; give it an FFMA fallback.
#if defined(__CUDA_ARCH_FEAT_SM103_ALL) ||                                        \
    (defined(__CUDA_ARCH_SPECIFIC__) && (__CUDA_ARCH_SPECIFIC__ == 1030)) ||      \
    (defined(__CUDA_ARCH_FAMILY_SPECIFIC__) && (__CUDA_ARCH_FAMILY_SPECIFIC__ == 1030))
#define HAS_TC 1
#else
#define HAS_TC 0
#endif

// ---------------- scratch (static device memory; no allocs) ----------------
__device__ uint4  g_hp[(size_t)N_NODES * 32];     // packed h  (hi<<16|lo per elem)
__device__ uint4  g_mp[(size_t)N_NODES * 32];     // packed m
__device__ uint4  g_wp[6 * 128 * 64];             // packed [Wl|Wr] per layer: [L][o][256k]
__device__ float4 g_raw[(size_t)N_NODES * 32];    // pre-norm fp32
__device__ int    g_deg[N_NODES];
__device__ int    g_rowptr[N_NODES + 1];
__device__ int    g_cursor[N_NODES];
__device__ int    g_col[N_EDGES];
__device__ float  g_stats[2 * NF];
__device__ float  g_scale[NF];
__device__ float  g_shift[NF];

// ---------------- small PTX helpers ----------------
__device__ __forceinline__ uint32_t smem_u32(const void* p) {
    uint32_t a;
    asm("{ .reg .u64 t; cvta.to.shared.u64 t, %1; cvt.u32.u64 %0, t; }" : "=r"(a) : "l"(p));
    return a;
}

// packed helpers: hi = bf16(v) bits, lo = bf16(v - hi) bits; word = hi<<16 | lo
__device__ __forceinline__ unsigned packf(float v) {
    unsigned hb = (unsigned)__bfloat16_as_ushort(__float2bfloat16(v));
    float hf = __uint_as_float(hb << 16);
    unsigned lb = (unsigned)__bfloat16_as_ushort(__float2bfloat16(v - hf));
    return (hb << 16) | lb;
}
__device__ __forceinline__ float unpackf(unsigned p) {
    return __uint_as_float(p & 0xFFFF0000u) + __uint_as_float(p << 16);
}

#if HAS_TC
__device__ __forceinline__ uint32_t elect_one() {
    uint32_t pred;
    asm volatile("{ .reg .pred p; elect.sync _|p, 0xFFFFFFFF; selp.b32 %0,1,0,p; }" : "=r"(pred));
    return pred;
}
#define MBAR_INIT(a, n) asm volatile("mbarrier.init.shared.b64 [%0], %1;" :: "r"(a), "r"(n) : "memory")
#define MBAR_WAIT(a, ph) do {                                                        \
    uint32_t _m = (a), _p = (ph), _d;                                                \
    asm volatile("{ .reg .pred p; mbarrier.try_wait.parity.acquire.cta.shared::cta.b64 p, [%1], %2;" \
                 " selp.b32 %0,1,0,p; }" : "=r"(_d) : "r"(_m), "r"(_p) : "memory");  \
    if (!_d) {                                                                       \
        asm volatile("{ .reg .pred P1; WL_%=:"                                       \
                     " mbarrier.try_wait.parity.acquire.cta.shared::cta.b64 P1, [%0], %1, 0x989680;" \
                     " @P1 bra.uni WD_%=; bra.uni WL_%=; WD_%=: }"                   \
                     :: "r"(_m), "r"(_p) : "memory");                                \
    } } while (0)
#define TC_ALLOC(sm, n)   asm volatile("tcgen05.alloc.cta_group::1.sync.aligned.shared::cta.b32 [%0], %1;" :: "r"(sm), "r"(n) : "memory")
#define TC_RELINQ()       asm volatile("tcgen05.relinquish_alloc_permit.cta_group::1.sync.aligned;")
#define TC_DEALLOC(t, n)  asm volatile("tcgen05.dealloc.cta_group::1.sync.aligned.b32 %0, %1;" :: "r"(t), "r"(n))
#define TC_COMMIT(mb)     asm volatile("tcgen05.commit.cta_group::1.mbarrier::arrive::one.shared::cluster.b64 [%0];" :: "r"(mb) : "memory")
#define TC_WAIT_LD()      asm volatile("tcgen05.wait::ld.sync.aligned;" ::: "memory")
#define TC_FENCE_AFTER()  asm volatile("tcgen05.fence::after_thread_sync;" ::: "memory")

#define TC_LD_X32(r, addr)                                                     \
    asm volatile("tcgen05.ld.sync.aligned.32x32b.x32.b32 "                     \
        "{%0,%1,%2,%3,%4,%5,%6,%7,%8,%9,%10,%11,%12,%13,%14,%15,"              \
        "%16,%17,%18,%19,%20,%21,%22,%23,%24,%25,%26,%27,%28,%29,%30,%31}, [%32];" \
        : "=r"((r)[0]),"=r"((r)[1]),"=r"((r)[2]),"=r"((r)[3]),                 \
          "=r"((r)[4]),"=r"((r)[5]),"=r"((r)[6]),"=r"((r)[7]),                 \
          "=r"((r)[8]),"=r"((r)[9]),"=r"((r)[10]),"=r"((r)[11]),               \
          "=r"((r)[12]),"=r"((r)[13]),"=r"((r)[14]),"=r"((r)[15]),             \
          "=r"((r)[16]),"=r"((r)[17]),"=r"((r)[18]),"=r"((r)[19]),             \
          "=r"((r)[20]),"=r"((r)[21]),"=r"((r)[22]),"=r"((r)[23]),             \
          "=r"((r)[24]),"=r"((r)[25]),"=r"((r)[26]),"=r"((r)[27]),             \
          "=r"((r)[28]),"=r"((r)[29]),"=r"((r)[30]),"=r"((r)[31])              \
        : "r"(addr))

static __device__ __forceinline__ uint64_t make_desc(uint32_t addr) {
    // SW128, Blackwell v1, LBO=1, SBO=64 (8 rows x 128B atom)
    const uint64_t base = (uint64_t(2) << 61) | (uint64_t(1) << 46) |
                          (uint64_t(64) << 32) | (uint64_t(1) << 16);
    return base | ((uint64_t)(addr >> 4) & 0x3FFF);
}
__device__ __forceinline__ void mma_f16_ss(uint32_t d, uint64_t a, uint64_t b,
                                           uint32_t idesc, uint32_t en) {
    asm volatile(
        "{ .reg .pred p; setp.ne.u32 p, %5, 0;"
        " tcgen05.mma.cta_group::1.kind::f16 [%0], %1, %2, %3, {%4,%4,%4,%4}, p; }"
        :: "r"(d), "l"(a), "l"(b), "r"(idesc), "r"(0u), "r"(en) : "memory");
}
#endif  // HAS_TC

// ---------------- CSR build ----------------
__global__ void k_zero_deg(int* deg) {
    int i = blockIdx.x * 256 + threadIdx.x;
    if (i < N_NODES) deg[i] = 0;
}
__global__ void k_count(const int* __restrict__ dst, int* __restrict__ deg) {
    int i = blockIdx.x * 256 + threadIdx.x;
    if (i < N_EDGES) atomicAdd(&deg[dst[i]], 1);
}
__global__ void k_scan(const int* __restrict__ deg, int* __restrict__ rowptr,
                       int* __restrict__ cursor) {
    __shared__ int sh[1024];
    int t = threadIdx.x;
    const int C = (N_NODES + 1023) / 1024;
    int base = t * C;
    int s = 0;
    for (int i = 0; i < C; i++) {
        int idx = base + i;
        if (idx < N_NODES) s += deg[idx];
    }
    sh[t] = s;
    __syncthreads();
    for (int d = 1; d < 1024; d <<= 1) {
        int v = (t >= d) ? sh[t - d] : 0;
        __syncthreads();
        sh[t] += v;
        __syncthreads();
    }
    int run = sh[t] - s;
    for (int i = 0; i < C; i++) {
        int idx = base + i;
        if (idx < N_NODES) {
            rowptr[idx] = run;
            cursor[idx] = run;
            run += deg[idx];
        }
    }
    if (t == 1023) rowptr[N_NODES] = sh[1023];
}
__global__ void k_fill(const int* __restrict__ src, const int* __restrict__ dst,
                       int* __restrict__ cursor, int* __restrict__ col) {
    int i = blockIdx.x * 256 + threadIdx.x;
    if (i < N_EDGES) {
        int d = dst[i];
        int p = atomicAdd(&cursor[d], 1);
        col[p] = src[i];
    }
}

// ---------------- conversions ----------------
__global__ void k_xconv(const float* __restrict__ x, unsigned* __restrict__ hp) {
    int i = blockIdx.x * 256 + threadIdx.x;
    if (i < N_NODES * NF) hp[i] = packf(x[i]);
}
__global__ void k_wconv(const float* __restrict__ Wl, const float* __restrict__ Wr,
                        unsigned* __restrict__ wp) {
    int i = blockIdx.x * 256 + threadIdx.x;
    if (i >= 6 * 128 * 256) return;
    int L = i >> 15;
    int rem = i & 32767;
    int o = rem >> 8;
    int k = rem & 255;
    float v = (k < 128) ? Wl[L * 16384 + o * 128 + k] : Wr[L * 16384 + o * 128 + (k - 128)];
    wp[i] = packf(v);
}

// ---------------- segment-max gather (packed in/out) ----------------
__global__ void k_gather(const uint4* __restrict__ hp, const int* __restrict__ rowptr,
                         const int* __restrict__ col, uint4* __restrict__ mp) {
    int node = blockIdx.x * 8 + (threadIdx.x >> 5);
    if (node >= N_NODES) return;
    int lane = threadIdx.x & 31;
    int beg = __ldg(&rowptr[node]);
    int end = __ldg(&rowptr[node + 1]);
    const float NINF = __int_as_float(0xff800000);
    float v0 = NINF, v1 = NINF, v2 = NINF, v3 = NINF;
    int e = beg;
    for (; e + 3 < end; e += 4) {
        int s0 = __ldg(&col[e]), s1 = __ldg(&col[e + 1]);
        int s2 = __ldg(&col[e + 2]), s3 = __ldg(&col[e + 3]);
        uint4 p0 = __ldg(&hp[(size_t)s0 * 32 + lane]);
        uint4 p1 = __ldg(&hp[(size_t)s1 * 32 + lane]);
        uint4 p2 = __ldg(&hp[(size_t)s2 * 32 + lane]);
        uint4 p3 = __ldg(&hp[(size_t)s3 * 32 + lane]);
        v0 = fmaxf(fmaxf(fmaxf(v0, unpackf(p0.x)), fmaxf(unpackf(p1.x), unpackf(p2.x))), unpackf(p3.x));
        v1 = fmaxf(fmaxf(fmaxf(v1, unpackf(p0.y)), fmaxf(unpackf(p1.y), unpackf(p2.y))), unpackf(p3.y));
        v2 = fmaxf(fmaxf(fmaxf(v2, unpackf(p0.z)), fmaxf(unpackf(p1.z), unpackf(p2.z))), unpackf(p3.z));
        v3 = fmaxf(fmaxf(fmaxf(v3, unpackf(p0.w)), fmaxf(unpackf(p1.w), unpackf(p2.w))), unpackf(p3.w));
    }
    for (; e < end; e++) {
        int s = __ldg(&col[e]);
        uint4 p = __ldg(&hp[(size_t)s * 32 + lane]);
        v0 = fmaxf(v0, unpackf(p.x));
        v1 = fmaxf(v1, unpackf(p.y));
        v2 = fmaxf(v2, unpackf(p.z));
        v3 = fmaxf(v3, unpackf(p.w));
    }
    if (beg == end) { v0 = v1 = v2 = v3 = 0.0f; }
    uint4 o;
    o.x = packf(v0); o.y = packf(v1); o.z = packf(v2); o.w = packf(v3);
    mp[(size_t)node * 32 + lane] = o;
}

// ---------------- fused dual GEMM + bias + column stats ----------------
// D[128x128] per CTA = A[128x256] @ W[128x256]^T, A=[m|h], W=[Wl|Wr],
// bf16x3 split (hi*hi + lo*hi + hi*lo), fp32 accum.
#define GEMM_DYN (131072 + 1024)

#if HAS_TC
#define IDESC_BF16 ((1u << 4) | (1u << 7) | (1u << 10) | (16u << 17) | (8u << 24))

__device__ __forceinline__ void load_tile(uint32_t sm_hi, uint32_t sm_lo,
                                          const uint4* __restrict__ gp4, int row_base,
                                          int row_limit, int ld_u, int col_u, int tid) {
#pragma unroll
    for (int it = 0; it < 8; it++) {
        int unit = it * 256 + tid;   // 0..2047  (128 rows x 16 units of 16B)
        int row = unit >> 4;
        int u = unit & 15;
        uint4 p = make_uint4(0u, 0u, 0u, 0u);
        int gr = row_base + row;
        if (gr < row_limit) p = __ldg(&gp4[(size_t)gr * ld_u + col_u + u]);
        unsigned hi0 = (p.x >> 16) | (p.y & 0xFFFF0000u);
        unsigned hi1 = (p.z >> 16) | (p.w & 0xFFFF0000u);
        unsigned lo0 = (p.x & 0xFFFFu) | (p.y << 16);
        unsigned lo1 = (p.z & 0xFFFFu) | (p.w << 16);
        uint32_t boff = row * 128 + u * 8;
        uint32_t sw = boff ^ ((boff >> 3) & 0x70);
        asm volatile("st.shared.v2.b32 [%0], {%1,%2};" :: "r"(sm_hi + sw), "r"(hi0), "r"(hi1));
        asm volatile("st.shared.v2.b32 [%0], {%1,%2};" :: "r"(sm_lo + sw), "r"(lo0), "r"(lo1));
    }
}
#endif

__global__ __launch_bounds__(256, 1)
void k_gemm(const uint4* __restrict__ Amp, const uint4* __restrict__ Ahp,
            const uint4* __restrict__ Wp, const float* __restrict__ bias,
            float4* __restrict__ out4, float* __restrict__ stats) {
    extern __shared__ char dyn[];
    int tid = threadIdx.x;
    int row0 = blockIdx.x * 128;
    float* stage = (float*)dyn;   // [128][132] fp32 result staging
    const uint32_t CTRL = 131072;
    float* sbias = (float*)(dyn + CTRL + 128);
    if (tid < 128) sbias[tid] = __ldg(&bias[tid]);

#if HAS_TC
    uint32_t sb = smem_u32(dyn);
    uint32_t mbar[2];
    mbar[0] = sb + CTRL;
    mbar[1] = sb + CTRL + 8;
    uint32_t tptr = sb + CTRL + 16;
    int wid = tid >> 5;
    int lane = tid & 31;

    if (wid == 0) { TC_ALLOC(tptr, 128); TC_RELINQ(); }
    if (tid == 0) { MBAR_INIT(mbar[0], 1); MBAR_INIT(mbar[1], 1); }
    __syncthreads();
    uint32_t tmem;
    asm volatile("ld.shared.b32 %0, [%1];" : "=r"(tmem) : "r"(tptr));

#pragma unroll 1
    for (int c = 0; c < 4; c++) {
        uint32_t so = sb + (c & 1) * 65536;
        if (c >= 2) { MBAR_WAIT(mbar[c & 1], 0); }
        const uint4* Ap = (c < 2) ? Amp : Ahp;
        load_tile(so, so + 16384, Ap, row0, N_NODES, 32, (c & 1) * 16, tid);
        load_tile(so + 32768, so + 49152, Wp, 0, 128, 64, c * 16, tid);
        asm volatile("fence.proxy.async.shared::cta;" ::: "memory");
        __syncthreads();
        if (wid == 0) {
            if (elect_one()) {
                uint64_t da_hi = make_desc(so);
                uint64_t da_lo = make_desc(so + 16384);
                uint64_t dw_hi = make_desc(so + 32768);
                uint64_t dw_lo = make_desc(so + 49152);
#pragma unroll
                for (int s = 0; s < 4; s++)
                    mma_f16_ss(tmem, da_hi + s * 2, dw_hi + s * 2, IDESC_BF16,
                               (c == 0 && s == 0) ? 0u : 1u);
#pragma unroll
                for (int s = 0; s < 4; s++)
                    mma_f16_ss(tmem, da_lo + s * 2, dw_hi + s * 2, IDESC_BF16, 1u);
#pragma unroll
                for (int s = 0; s < 4; s++)
                    mma_f16_ss(tmem, da_hi + s * 2, dw_lo + s * 2, IDESC_BF16, 1u);
                TC_COMMIT(mbar[c & 1]);
            }
        }
    }
    MBAR_WAIT(mbar[1], 1);
    TC_FENCE_AFTER();

    if (wid < 4) {
        uint32_t dr[128];
        TC_LD_X32(dr, tmem);
        TC_LD_X32(dr + 32, tmem + 32);
        TC_LD_X32(dr + 64, tmem + 64);
        TC_LD_X32(dr + 96, tmem + 96);
        TC_WAIT_LD();
        int r = wid * 32 + lane;
        bool valid = (row0 + r) < N_NODES;
#pragma unroll
        for (int cc = 0; cc < 128; cc++)
            stage[r * 132 + cc] = valid ? (__uint_as_float(dr[cc]) + sbias[cc]) : 0.0f;
    }
    __syncthreads();
#else
    // Fallback FFMA path (compute_103 PTX target only; never selected on GB300 —
    // the fat binary's sm_103a cubin takes precedence at module load).
    __syncthreads();
    for (int half = 0; half < 2; half++) {
        int r = (tid >> 1);
        int c0 = (tid & 1) * 32 + half * 64;
        float acc[32];
#pragma unroll
        for (int j = 0; j < 32; j++) acc[j] = 0.0f;
        int gr = row0 + r;
        if (gr < N_NODES) {
            for (int k = 0; k < 256; k++) {
                unsigned aw = ((const unsigned*)((k < 128) ? Amp : Ahp))[(size_t)gr * 128 + (k & 127)];
                float av = unpackf(aw);
#pragma unroll
                for (int j = 0; j < 32; j++) {
                    unsigned ww = ((const unsigned*)Wp)[(size_t)(c0 + j) * 256 + k];
                    acc[j] += av * unpackf(ww);
                }
            }
        }
#pragma unroll
        for (int j = 0; j < 32; j++)
            stage[r * 132 + c0 + j] = (gr < N_NODES) ? (acc[j] + sbias[c0 + j]) : 0.0f;
    }
    __syncthreads();
#endif

    // common epilogue: column stats + coalesced store
    if (tid < 128) {
        float s = 0.f, s2 = 0.f;
#pragma unroll 8
        for (int r = 0; r < 128; r++) {
            float v = stage[r * 132 + tid];
            s += v;
            s2 += v * v;
        }
        atomicAdd(&stats[tid], s);
        atomicAdd(&stats[128 + tid], s2);
    }
#pragma unroll
    for (int it = 0; it < 16; it++) {
        int idx = it * 256 + tid;
        int row = idx >> 5, c4 = idx & 31;
        int gr = row0 + row;
        if (gr < N_NODES) {
            float4 o;
            o.x = stage[row * 132 + c4 * 4 + 0];
            o.y = stage[row * 132 + c4 * 4 + 1];
            o.z = stage[row * 132 + c4 * 4 + 2];
            o.w = stage[row * 132 + c4 * 4 + 3];
            out4[(size_t)gr * 32 + c4] = o;
        }
    }
#if HAS_TC
    __syncthreads();
    if ((tid >> 5) == 0) TC_DEALLOC(tmem, 128);
#endif
}

// ---------------- GraphNorm stats + normalize ----------------
__global__ void k_zero_stats(float* st) { st[threadIdx.x] = 0.f; }

__global__ void k_stats(const float* __restrict__ st, const float* __restrict__ gamma,
                        const float* __restrict__ beta, const float* __restrict__ alpha,
                        float* __restrict__ scale, float* __restrict__ shift) {
    int c = threadIdx.x;
    const float invN = 1.0f / (float)N_NODES;
    float mu = st[c] * invN;
    float a = alpha[c];
    float var = st[c + 128] * invN + mu * mu * (a * a - 2.f * a);
    float r = rsqrtf(var + EPSN);
    float g = gamma[c];
    scale[c] = g * r;
    shift[c] = beta[c] - g * a * mu * r;
}

__global__ void k_norm(const float4* __restrict__ raw, const float4* __restrict__ sc4,
                       const float4* __restrict__ sh4, uint4* __restrict__ hp) {
    int i = blockIdx.x * 256 + threadIdx.x;
    if (i >= N_NODES * 32) return;
    int c4 = i & 31;
    float4 s = __ldg(&sc4[c4]);
    float4 t = __ldg(&sh4[c4]);
    float4 v = raw[i];
    float4 o;
    o.x = s.x * v.x + t.x; o.x = (o.x > 0.f) ? o.x : NEG_SLOPE * o.x;
    o.y = s.y * v.y + t.y; o.y = (o.y > 0.f) ? o.y : NEG_SLOPE * o.y;
    o.z = s.z * v.z + t.z; o.z = (o.z > 0.f) ? o.z : NEG_SLOPE * o.z;
    o.w = s.w * v.w + t.w; o.w = (o.w > 0.f) ? o.w : NEG_SLOPE * o.w;
    uint4 p;
    p.x = packf(o.x); p.y = packf(o.y); p.z = packf(o.z); p.w = packf(o.w);
    hp[i] = p;
}

// ---------------- final SAGEConv (NF->3) + tanh*0.5 ----------------
__global__ void k_final(const uint4* __restrict__ mp, const uint4* __restrict__ hp,
                        const float* __restrict__ Wlo, const float* __restrict__ Wro,
                        const float* __restrict__ blo, float* __restrict__ out) {
    __shared__ float4 swl[3][32];
    __shared__ float4 swr[3][32];
    __shared__ float sb[3];
    int tid = threadIdx.x;
    if (tid < 96) {
        int o = tid >> 5, l = tid & 31;
        swl[o][l] = ((const float4*)Wlo)[o * 32 + l];
        swr[o][l] = ((const float4*)Wro)[o * 32 + l];
    }
    if (tid < 3) sb[tid] = blo[tid];
    __syncthreads();

    int node = blockIdx.x * 8 + (tid >> 5);
    if (node >= N_NODES) return;
    int lane = tid & 31;
    uint4 mv4 = mp[(size_t)node * 32 + lane];
    uint4 hv4 = hp[(size_t)node * 32 + lane];
    float mv[4] = {unpackf(mv4.x), unpackf(mv4.y), unpackf(mv4.z), unpackf(mv4.w)};
    float hv[4] = {unpackf(hv4.x), unpackf(hv4.y), unpackf(hv4.z), unpackf(hv4.w)};
    float p[3];
#pragma unroll
    for (int o = 0; o < 3; o++) {
        float4 wl = swl[o][lane];
        float4 wr = swr[o][lane];
        p[o] = mv[0] * wl.x + mv[1] * wl.y + mv[2] * wl.z + mv[3] * wl.w +
               hv[0] * wr.x + hv[1] * wr.y + hv[2] * wr.z + hv[3] * wr.w;
    }
#pragma unroll
    for (int d = 16; d; d >>= 1) {
#pragma unroll
        for (int o = 0; o < 3; o++) p[o] += __shfl_down_sync(0xffffffffu, p[o], d);
    }
    if (lane == 0) {
#pragma unroll
        for (int o = 0; o < 3; o++)
            out[(size_t)node * 3 + o] = tanhf(p[o] + sb[o]) * 0.5f;
    }
}

// ---------------- host launcher ----------------
extern "C" void kernel_launch(void* const* d_in, const int* in_sizes, int n_in,
                              void* d_out, int out_size) {
    const float* x     = (const float*)d_in[0];
    const int*   ei    = (const int*)d_in[1];
    const float* Wl    = (const float*)d_in[2];
    const float* bl    = (const float*)d_in[3];
    const float* Wr    = (const float*)d_in[4];
    const float* Wlo   = (const float*)d_in[5];
    const float* blo   = (const float*)d_in[6];
    const float* Wro   = (const float*)d_in[7];
    const float* gamma = (const float*)d_in[8];
    const float* beta  = (const float*)d_in[9];
    const float* alpha = (const float*)d_in[10];

    uint4 *hp, *mpv, *wp;
    float4 *raw;
    float *stats, *scale, *shift;
    int *deg, *rowptr, *cursor, *col;
    cudaGetSymbolAddress((void**)&hp, g_hp);
    cudaGetSymbolAddress((void**)&mpv, g_mp);
    cudaGetSymbolAddress((void**)&wp, g_wp);
    cudaGetSymbolAddress((void**)&raw, g_raw);
    cudaGetSymbolAddress((void**)&stats, g_stats);
    cudaGetSymbolAddress((void**)&scale, g_scale);
    cudaGetSymbolAddress((void**)&shift, g_shift);
    cudaGetSymbolAddress((void**)&deg, g_deg);
    cudaGetSymbolAddress((void**)&rowptr, g_rowptr);
    cudaGetSymbolAddress((void**)&cursor, g_cursor);
    cudaGetSymbolAddress((void**)&col, g_col);

    cudaFuncSetAttribute(k_gemm, cudaFuncAttributeMaxDynamicSharedMemorySize, GEMM_DYN);

    const int* src = ei;
    const int* dst = ei + N_EDGES;

    // CSR build
    k_zero_deg<<<(N_NODES + 255) / 256, 256>>>(deg);
    k_count<<<(N_EDGES + 255) / 256, 256>>>(dst, deg);
    k_scan<<<1, 1024>>>(deg, rowptr, cursor);
    k_fill<<<(N_EDGES + 255) / 256, 256>>>(src, dst, cursor, col);

    // conversions
    k_xconv<<<(N_NODES * NF + 255) / 256, 256>>>(x, (unsigned*)hp);
    k_wconv<<<(6 * 128 * 256 + 255) / 256, 256>>>(Wl, Wr, (unsigned*)wp);

    const int gemm_grid = (N_NODES + 127) / 128;
    for (int L = 0; L < 6; L++) {
        k_gather<<<(N_NODES + 7) / 8, 256>>>(hp, rowptr, col, mpv);
        k_zero_stats<<<1, 256>>>(stats);
        k_gemm<<<gemm_grid, 256, GEMM_DYN>>>(mpv, hp, wp + (size_t)L * 128 * 64,
                                             bl + L * NF, raw, stats);
        k_stats<<<1, 128>>>(stats, gamma + L * NF, beta + L * NF, alpha + L * NF,
                            scale, shift);
        k_norm<<<(N_NODES * 32 + 255) / 256, 256>>>(raw, (const float4*)scale,
                                                    (const float4*)shift, hp);
    }
    k_gather<<<(N_NODES + 7) / 8, 256>>>(hp, rowptr, col, mpv);
    k_final<<<(N_NODES + 7) / 8, 256>>>(mpv, hp, Wlo, Wro, blo, (float*)d_out);
}